// round 7
// baseline (speedup 1.0000x reference)
#include <cuda_runtime.h>
#include <cuda_fp16.h>
#include <cstdint>

// ---------------------------------------------------------------------------
// Tri-plane sampling, channel-last fp16 scratch:
//   phase 1: fused transpose of 9 grids [32,R,R] -> [R*R,32] fp16 (66 MB,
//            L2-resident). 256-px tiles, float4 loads, uint4 stores.
//   phase 2: 4 points/warp, 8 lanes/point. One LDG.128 per row fetches both
//            x-corners; y-lerp + x-lerp in packed half2 (HFMA2), x-exchange
//            via 4 shfl_xor; lane converts only the 16B it stores.
// ---------------------------------------------------------------------------

#define TOTAL_PX 1032192u   // 3*128^2 + 3*256^2 + 3*512^2
// 4 uint4 per pixel (32 x fp16); +4 pad for the x-edge row-pair overread
__device__ uint4 g_buf[TOTAL_PX * 4 + 4];   // 66 MB, 16B-aligned

__constant__ unsigned c_base_px[9] = {0u,      16384u,  32768u,
                                      49152u,  114688u, 180224u,
                                      245760u, 507904u, 770048u};
__constant__ int      c_npix[9]    = {16384, 16384, 16384,
                                      65536, 65536, 65536,
                                      262144, 262144, 262144};
// tile_start[i] = base_px[i] / 256  (256 pixels per block)
__constant__ int      c_tile_start[9] = {0, 64, 128, 192,
                                         448, 704, 960, 1984, 3008};
#define TOTAL_TILES 4032    // TOTAL_PX / 256

struct GridPtrs { const float* g[9]; };

__global__ void __launch_bounds__(256)
transpose_all(GridPtrs ptrs) {
    // [channel][pixel], row stride 260 floats: 16B-aligned rows (1040B),
    // conflict-free float4 stores ((260/4) mod 8 = 1) and LDS reads (px-major).
    __shared__ float tile[32][260];
    const int b = blockIdx.x;

    int gi = 0;
    #pragma unroll
    for (int i = 1; i < 9; i++)
        if (b >= c_tile_start[i]) gi = i;

    const float* __restrict__ g = ptrs.g[gi];
    const int npix = c_npix[gi];
    const int pix0 = (b - c_tile_start[gi]) * 256;

    const int t  = threadIdx.x;
    const int c  = t >> 3;   // channel 0..31
    const int f0 = t & 7;    // float4 slot

    // load: 64 float4 per channel row, 8 per thread, 128B-coalesced
    const float4* row  = (const float4*)(g + (size_t)c * npix + pix0);
    float4*       srow = (float4*)&tile[c][0];
    #pragma unroll
    for (int j = 0; j < 8; j++)
        srow[f0 + 8 * j] = __ldg(row + f0 + 8 * j);
    __syncthreads();

    // store: one pixel per thread -> 4 uint4 = 64B contiguous per lane,
    // warp covers 2KB fully coalesced
    const int pix = t;
    uint4* dst = g_buf + ((size_t)c_base_px[gi] + pix0 + pix) * 4;
    #pragma unroll
    for (int q = 0; q < 4; q++) {
        unsigned int w[4];
        #pragma unroll
        for (int k = 0; k < 4; k++) {
            const __half2 hh = __floats2half2_rn(tile[8 * q + 2 * k][pix],
                                                 tile[8 * q + 2 * k + 1][pix]);
            w[k] = *(const unsigned int*)&hh;
        }
        dst[q] = make_uint4(w[0], w[1], w[2], w[3]);
    }
}

__global__ void __launch_bounds__(256)
sample_kernel(const float* __restrict__ pts, float* __restrict__ out, int n) {
    const int warp = (int)((blockIdx.x * 256u + threadIdx.x) >> 5);
    const int lane = threadIdx.x & 31;
    const int s    = lane & 7;            // 16B chunk of the 128B row-pair
    const int pt   = warp * 4 + (lane >> 3);
    const int ptc  = min(pt, n - 1);      // clamp so shuffles stay full-warp
    const bool live = (pt < n);

    const float vx = __ldg(pts + 3 * (size_t)ptc + 0);
    const float vy = __ldg(pts + 3 * (size_t)ptc + 1);
    const float vz = __ldg(pts + 3 * (size_t)ptc + 2);

    // p = (v - 1.6) * (-0.625) - 1
    const float px = (vx - 1.6f) * (-0.625f) - 1.0f;
    const float py = (vy - 1.6f) * (-0.625f) - 1.0f;
    const float pz = (vz - 1.6f) * (-0.625f) - 1.0f;

    const float cw[3] = {py, px, px};   // plane -> W coord
    const float ch[3] = {pz, pz, py};   // plane -> H coord

    const int Rs[3] = {128, 256, 512};
    const unsigned base_px[9] = {0u,      16384u,  32768u,
                                 49152u,  114688u, 180224u,
                                 245760u, 507904u, 770048u};

    const bool isR = (s >= 4);   // lane holds the x1 (right) corner after load
    // lane stores channels [8*(s&3) + 4*(s>>2) .. +4)
    float* outp = out + (size_t)ptc * 288 + 8 * (s & 3) + 4 * (s >> 2);

    #pragma unroll
    for (int l = 0; l < 3; l++) {
        const int   R   = Rs[l];
        const float Rm1 = (float)(R - 1);
        #pragma unroll
        for (int p = 0; p < 3; p++) {
            float x = (cw[p] + 1.0f) * 0.5f * Rm1;
            x = fminf(fmaxf(x, 0.0f), Rm1);
            float y = (ch[p] + 1.0f) * 0.5f * Rm1;
            y = fminf(fmaxf(y, 0.0f), Rm1);

            const float x0f = floorf(x), y0f = floorf(y);
            const float wx = x - x0f,    wy = y - y0f;
            const int x0 = (int)x0f,     y0 = (int)y0f;
            const int y1 = min(y0 + 1, R - 1);
            // x1 implicit: the 128B row-pair covers x0 and x0+1; at x0==R-1,
            // wx==0 so the (padded, in-bounds) overread has zero weight.

            const __half2 wy2  = __float2half2_rn(wy);
            const __half2 iwy2 = __float2half2_rn(1.0f - wy);
            const __half2 wx2  = __float2half2_rn(wx);
            const __half2 iwx2 = __float2half2_rn(1.0f - wx);

            const uint4* base = g_buf + ((size_t)base_px[l * 3 + p] << 2) + s;
            const uint4 a = __ldg(base + ((size_t)(y0 * R + x0) << 2));  // row y0
            const uint4 b = __ldg(base + ((size_t)(y1 * R + x0) << 2));  // row y1

            // y-lerp in half2: 8 channels of this lane's x-corner
            unsigned int ry[4];
            #pragma unroll
            for (int k = 0; k < 4; k++) {
                const unsigned int ua = (&a.x)[k], ub = (&b.x)[k];
                const __half2 v = __hfma2(*(const __half2*)&ub, wy2,
                                          __hmul2(*(const __half2*)&ua, iwy2));
                ry[k] = *(const unsigned int*)&v;
            }

            // exchange with partner x-corner (lane ^ 4), x-lerp in half2
            unsigned int res[4];
            #pragma unroll
            for (int k = 0; k < 4; k++) {
                const unsigned int o = __shfl_xor_sync(0xffffffffu, ry[k], 4);
                const unsigned int ulo = isR ? o     : ry[k];   // x0 corner
                const unsigned int uhi = isR ? ry[k] : o;       // x1 corner
                const __half2 v = __hfma2(*(const __half2*)&uhi, wx2,
                                          __hmul2(*(const __half2*)&ulo, iwx2));
                res[k] = *(const unsigned int*)&v;
            }

            // partners hold identical res; each lane converts/stores only its
            // half: words {0,1} for left lanes, {2,3} for right lanes.
            if (live) {
                const unsigned int w0 = isR ? res[2] : res[0];
                const unsigned int w1 = isR ? res[3] : res[1];
                const float2 f0 = __half22float2(*(const __half2*)&w0);
                const float2 f1 = __half22float2(*(const __half2*)&w1);
                float4 v; v.x = f0.x; v.y = f0.y; v.z = f1.x; v.w = f1.y;
                *(float4*)(outp + (l * 3 + p) * 32) = v;   // one STG.128/line
            }
        }
    }
}

extern "C" void kernel_launch(void* const* d_in, const int* in_sizes, int n_in,
                              void* d_out, int out_size) {
    const float* pts = (const float*)d_in[0];
    const int n = in_sizes[0] / 3;  // 300000 points

    GridPtrs ptrs;
    for (int i = 0; i < 9; i++) ptrs.g[i] = (const float*)d_in[1 + i];

    transpose_all<<<TOTAL_TILES, 256>>>(ptrs);

    // 4 points per warp, 8 warps per block -> 32 points per block
    const int blocks = (n + 31) / 32;
    sample_kernel<<<blocks, 256>>>(pts, (float*)d_out, n);
}

// round 8
// speedup vs baseline: 1.0458x; 1.0458x over previous
#include <cuda_runtime.h>
#include <cuda_fp16.h>
#include <cstdint>

// ---------------------------------------------------------------------------
// Tri-plane sampling, channel-last fp16 scratch:
//   phase 1: fused transpose of 9 grids [32,R,R] -> [R*R,32] fp16 (66 MB,
//            L2-resident). 256-px tiles; float4 LDG; smem [ch][265] (odd
//            stride => conflict-free scalar STS and LDS); STG.128 with
//            lane = 4*pix + chunk => 512B contiguous per instruction.
//   phase 2: 4 points/warp, 8 lanes/point. One LDG.128 per row fetches both
//            x-corners; y-lerp + x-lerp in packed half2 (HFMA2), x-exchange
//            via 4 shfl_xor; lane converts only the 16B it stores.
// ---------------------------------------------------------------------------

#define TOTAL_PX 1032192u   // 3*128^2 + 3*256^2 + 3*512^2
// 4 uint4 per pixel (32 x fp16); +4 pad for the x-edge row-pair overread
__device__ uint4 g_buf[TOTAL_PX * 4 + 4];   // 66 MB, 16B-aligned

__constant__ unsigned c_base_px[9] = {0u,      16384u,  32768u,
                                      49152u,  114688u, 180224u,
                                      245760u, 507904u, 770048u};
__constant__ int      c_npix[9]    = {16384, 16384, 16384,
                                      65536, 65536, 65536,
                                      262144, 262144, 262144};
// tile_start[i] = base_px[i] / 256  (256 pixels per block)
__constant__ int      c_tile_start[9] = {0, 64, 128, 192,
                                         448, 704, 960, 1984, 3008};
#define TOTAL_TILES 4032    // TOTAL_PX / 256

struct GridPtrs { const float* g[9]; };

__global__ void __launch_bounds__(256)
transpose_all(GridPtrs ptrs) {
    // [channel][pixel], row stride 265 floats (odd; 265 mod 32 = 9):
    //  - phase-1 scalar STS: bank = 9c + 4*f0 + i  -> bijective over warp
    //  - phase-2 scalar LDS: bank = 8q + pix       -> bijective over warp
    __shared__ float tile[32][265];
    const int b = blockIdx.x;

    int gi = 0;
    #pragma unroll
    for (int i = 1; i < 9; i++)
        if (b >= c_tile_start[i]) gi = i;

    const float* __restrict__ g = ptrs.g[gi];
    const int npix = c_npix[gi];
    const int pix0 = (b - c_tile_start[gi]) * 256;

    const int t  = threadIdx.x;
    const int c  = t >> 3;   // channel 0..31
    const int f0 = t & 7;    // float4 slot

    // phase 1: 64 float4 per channel row, 8 per thread, 128B-coalesced LDG;
    // scatter into smem with conflict-free scalar stores.
    const float4* row = (const float4*)(g + (size_t)c * npix + pix0);
    #pragma unroll
    for (int j = 0; j < 8; j++) {
        const float4 v = __ldg(row + f0 + 8 * j);
        const int px = 4 * (f0 + 8 * j);
        tile[c][px + 0] = v.x;
        tile[c][px + 1] = v.y;
        tile[c][px + 2] = v.z;
        tile[c][px + 3] = v.w;
    }
    __syncthreads();

    // phase 2: warp owns 32 pixels; per step 8 pixels, lane = 4*pix + chunk.
    // Each thread packs channels [8q, 8q+8) of its pixel into one uint4.
    // STG.128: consecutive lanes -> consecutive 16B => 512B contiguous/instr.
    const int lane = t & 31;
    const int wrp  = t >> 5;           // 0..7
    const int q    = lane & 3;         // chunk: channels [8q, 8q+8)
    const int pl   = lane >> 2;        // pixel within group of 8

    uint4* dstb = g_buf + ((size_t)c_base_px[gi] + pix0) * 4;
    #pragma unroll
    for (int s = 0; s < 4; s++) {
        const int pix = wrp * 32 + s * 8 + pl;
        unsigned int w[4];
        #pragma unroll
        for (int k = 0; k < 4; k++) {
            const __half2 hh = __floats2half2_rn(tile[8 * q + 2 * k][pix],
                                                 tile[8 * q + 2 * k + 1][pix]);
            w[k] = *(const unsigned int*)&hh;
        }
        dstb[(size_t)pix * 4 + q] = make_uint4(w[0], w[1], w[2], w[3]);
    }
}

__global__ void __launch_bounds__(256)
sample_kernel(const float* __restrict__ pts, float* __restrict__ out, int n) {
    const int warp = (int)((blockIdx.x * 256u + threadIdx.x) >> 5);
    const int lane = threadIdx.x & 31;
    const int s    = lane & 7;            // 16B chunk of the 128B row-pair
    const int pt   = warp * 4 + (lane >> 3);
    const int ptc  = min(pt, n - 1);      // clamp so shuffles stay full-warp
    const bool live = (pt < n);

    const float vx = __ldg(pts + 3 * (size_t)ptc + 0);
    const float vy = __ldg(pts + 3 * (size_t)ptc + 1);
    const float vz = __ldg(pts + 3 * (size_t)ptc + 2);

    // p = (v - 1.6) * (-0.625) - 1
    const float px = (vx - 1.6f) * (-0.625f) - 1.0f;
    const float py = (vy - 1.6f) * (-0.625f) - 1.0f;
    const float pz = (vz - 1.6f) * (-0.625f) - 1.0f;

    const float cw[3] = {py, px, px};   // plane -> W coord
    const float ch[3] = {pz, pz, py};   // plane -> H coord

    const int Rs[3] = {128, 256, 512};
    const unsigned base_px[9] = {0u,      16384u,  32768u,
                                 49152u,  114688u, 180224u,
                                 245760u, 507904u, 770048u};

    const bool isR = (s >= 4);   // lane holds the x1 (right) corner after load
    // lane stores channels [8*(s&3) + 4*(s>>2) .. +4)
    float* outp = out + (size_t)ptc * 288 + 8 * (s & 3) + 4 * (s >> 2);

    #pragma unroll
    for (int l = 0; l < 3; l++) {
        const int   R   = Rs[l];
        const float Rm1 = (float)(R - 1);
        #pragma unroll
        for (int p = 0; p < 3; p++) {
            float x = (cw[p] + 1.0f) * 0.5f * Rm1;
            x = fminf(fmaxf(x, 0.0f), Rm1);
            float y = (ch[p] + 1.0f) * 0.5f * Rm1;
            y = fminf(fmaxf(y, 0.0f), Rm1);

            const float x0f = floorf(x), y0f = floorf(y);
            const float wx = x - x0f,    wy = y - y0f;
            const int x0 = (int)x0f,     y0 = (int)y0f;
            const int y1 = min(y0 + 1, R - 1);
            // x1 implicit: the 128B row-pair covers x0 and x0+1; at x0==R-1,
            // wx==0 so the (padded, in-bounds) overread has zero weight.

            const __half2 wy2  = __float2half2_rn(wy);
            const __half2 iwy2 = __float2half2_rn(1.0f - wy);
            const __half2 wx2  = __float2half2_rn(wx);
            const __half2 iwx2 = __float2half2_rn(1.0f - wx);

            const uint4* base = g_buf + ((size_t)base_px[l * 3 + p] << 2) + s;
            const uint4 a = __ldg(base + ((size_t)(y0 * R + x0) << 2));  // row y0
            const uint4 b = __ldg(base + ((size_t)(y1 * R + x0) << 2));  // row y1

            // y-lerp in half2: 8 channels of this lane's x-corner
            unsigned int ry[4];
            #pragma unroll
            for (int k = 0; k < 4; k++) {
                const unsigned int ua = (&a.x)[k], ub = (&b.x)[k];
                const __half2 v = __hfma2(*(const __half2*)&ub, wy2,
                                          __hmul2(*(const __half2*)&ua, iwy2));
                ry[k] = *(const unsigned int*)&v;
            }

            // exchange with partner x-corner (lane ^ 4), x-lerp in half2
            unsigned int res[4];
            #pragma unroll
            for (int k = 0; k < 4; k++) {
                const unsigned int o = __shfl_xor_sync(0xffffffffu, ry[k], 4);
                const unsigned int ulo = isR ? o     : ry[k];   // x0 corner
                const unsigned int uhi = isR ? ry[k] : o;       // x1 corner
                const __half2 v = __hfma2(*(const __half2*)&uhi, wx2,
                                          __hmul2(*(const __half2*)&ulo, iwx2));
                res[k] = *(const unsigned int*)&v;
            }

            // partners hold identical res; each lane converts/stores only its
            // half: words {0,1} for left lanes, {2,3} for right lanes.
            if (live) {
                const unsigned int w0 = isR ? res[2] : res[0];
                const unsigned int w1 = isR ? res[3] : res[1];
                const float2 f0 = __half22float2(*(const __half2*)&w0);
                const float2 f1 = __half22float2(*(const __half2*)&w1);
                float4 v; v.x = f0.x; v.y = f0.y; v.z = f1.x; v.w = f1.y;
                *(float4*)(outp + (l * 3 + p) * 32) = v;   // one STG.128/line
            }
        }
    }
}

extern "C" void kernel_launch(void* const* d_in, const int* in_sizes, int n_in,
                              void* d_out, int out_size) {
    const float* pts = (const float*)d_in[0];
    const int n = in_sizes[0] / 3;  // 300000 points

    GridPtrs ptrs;
    for (int i = 0; i < 9; i++) ptrs.g[i] = (const float*)d_in[1 + i];

    transpose_all<<<TOTAL_TILES, 256>>>(ptrs);

    // 4 points per warp, 8 warps per block -> 32 points per block
    const int blocks = (n + 31) / 32;
    sample_kernel<<<blocks, 256>>>(pts, (float*)d_out, n);
}

// round 9
// speedup vs baseline: 1.1310x; 1.0815x over previous
#include <cuda_runtime.h>
#include <cuda_fp16.h>
#include <cstdint>

// ---------------------------------------------------------------------------
// Tri-plane sampling, channel-last fp16 scratch:
//   phase 1: fused transpose of 9 grids [32,R,R] -> [R*R,32] fp16 (66 MB,
//            L2-resident). R5's measured-best structure (128-px tiles,
//            conflict-free smem, paired half2 stores) + __ldcs grid reads
//            (evict-first: grids are never re-read).
//   phase 2: 4 points/warp, 8 lanes/point. One LDG.128 per row fetches both
//            x-corners; half2 lerps + shfl_xor x-exchange; output stored
//            with __stcs (streaming) so the 345 MB write doesn't evict the
//            scratch from L2.
// ---------------------------------------------------------------------------

#define TOTAL_PX 1032192u   // 3*128^2 + 3*256^2 + 3*512^2
// 4 uint4 per pixel (32 x fp16); +4 pad for the x-edge row-pair overread
__device__ uint4 g_buf[TOTAL_PX * 4 + 4];   // 66 MB, 16B-aligned

__constant__ unsigned c_base_px[9] = {0u,      16384u,  32768u,
                                      49152u,  114688u, 180224u,
                                      245760u, 507904u, 770048u};
__constant__ int      c_npix[9]    = {16384, 16384, 16384,
                                      65536, 65536, 65536,
                                      262144, 262144, 262144};
// tile_start[i] = base_px[i] / 128  (128 pixels per block)
__constant__ int      c_tile_start[9] = {0, 128, 256,
                                         384, 896, 1408,
                                         1920, 3968, 6016};
#define TOTAL_TILES 8064    // TOTAL_PX / 128

struct GridPtrs { const float* g[9]; };

__global__ void __launch_bounds__(256)
transpose_all(GridPtrs ptrs) {
    __shared__ float tile[128][33];   // stride 33: conflict-free both phases
    const int b = blockIdx.x;

    int gi = 0;
    #pragma unroll
    for (int i = 1; i < 9; i++)
        if (b >= c_tile_start[i]) gi = i;

    const float* __restrict__ g = ptrs.g[gi];
    const int npix = c_npix[gi];
    const int pix0 = (b - c_tile_start[gi]) * 128;

    const int tx = threadIdx.x & 31;
    const int ty = threadIdx.x >> 5;   // warp id 0..7

    #pragma unroll
    for (int c = ty; c < 32; c += 8) {
        const float* row = g + (size_t)c * npix + pix0;
        #pragma unroll
        for (int j = 0; j < 4; j++)
            tile[32 * j + tx][c] = __ldcs(row + 32 * j + tx);  // evict-first
    }
    __syncthreads();

    __half2* dst = (__half2*)g_buf + ((size_t)c_base_px[gi] + pix0) * 16;
    const int hl = tx & 15;
    #pragma unroll
    for (int s = 0; s < 8; s++) {
        const int pix = ty * 16 + s * 2 + (tx >> 4);
        const float a  = tile[pix][2 * hl];
        const float c2 = tile[pix][2 * hl + 1];
        dst[(size_t)pix * 16 + hl] = __floats2half2_rn(a, c2);
    }
}

__global__ void __launch_bounds__(256)
sample_kernel(const float* __restrict__ pts, float* __restrict__ out, int n) {
    const int warp = (int)((blockIdx.x * 256u + threadIdx.x) >> 5);
    const int lane = threadIdx.x & 31;
    const int s    = lane & 7;            // 16B chunk of the 128B row-pair
    const int pt   = warp * 4 + (lane >> 3);
    const int ptc  = min(pt, n - 1);      // clamp so shuffles stay full-warp
    const bool live = (pt < n);

    const float vx = __ldg(pts + 3 * (size_t)ptc + 0);
    const float vy = __ldg(pts + 3 * (size_t)ptc + 1);
    const float vz = __ldg(pts + 3 * (size_t)ptc + 2);

    // p = (v - 1.6) * (-0.625) - 1
    const float px = (vx - 1.6f) * (-0.625f) - 1.0f;
    const float py = (vy - 1.6f) * (-0.625f) - 1.0f;
    const float pz = (vz - 1.6f) * (-0.625f) - 1.0f;

    const float cw[3] = {py, px, px};   // plane -> W coord
    const float ch[3] = {pz, pz, py};   // plane -> H coord

    const int Rs[3] = {128, 256, 512};
    const unsigned base_px[9] = {0u,      16384u,  32768u,
                                 49152u,  114688u, 180224u,
                                 245760u, 507904u, 770048u};

    const bool isR = (s >= 4);   // lane holds the x1 (right) corner after load
    // lane stores channels [8*(s&3) + 4*(s>>2) .. +4)
    float* outp = out + (size_t)ptc * 288 + 8 * (s & 3) + 4 * (s >> 2);

    #pragma unroll
    for (int l = 0; l < 3; l++) {
        const int   R   = Rs[l];
        const float Rm1 = (float)(R - 1);
        #pragma unroll
        for (int p = 0; p < 3; p++) {
            float x = (cw[p] + 1.0f) * 0.5f * Rm1;
            x = fminf(fmaxf(x, 0.0f), Rm1);
            float y = (ch[p] + 1.0f) * 0.5f * Rm1;
            y = fminf(fmaxf(y, 0.0f), Rm1);

            const float x0f = floorf(x), y0f = floorf(y);
            const float wx = x - x0f,    wy = y - y0f;
            const int x0 = (int)x0f,     y0 = (int)y0f;
            const int y1 = min(y0 + 1, R - 1);
            // x1 implicit: the 128B row-pair covers x0 and x0+1; at x0==R-1,
            // wx==0 so the (padded, in-bounds) overread has zero weight.

            const __half2 wy2  = __float2half2_rn(wy);
            const __half2 iwy2 = __float2half2_rn(1.0f - wy);
            const __half2 wx2  = __float2half2_rn(wx);
            const __half2 iwx2 = __float2half2_rn(1.0f - wx);

            const uint4* base = g_buf + ((size_t)base_px[l * 3 + p] << 2) + s;
            const uint4 a = __ldg(base + ((size_t)(y0 * R + x0) << 2));  // row y0
            const uint4 b = __ldg(base + ((size_t)(y1 * R + x0) << 2));  // row y1

            // y-lerp in half2: 8 channels of this lane's x-corner
            unsigned int ry[4];
            #pragma unroll
            for (int k = 0; k < 4; k++) {
                const unsigned int ua = (&a.x)[k], ub = (&b.x)[k];
                const __half2 v = __hfma2(*(const __half2*)&ub, wy2,
                                          __hmul2(*(const __half2*)&ua, iwy2));
                ry[k] = *(const unsigned int*)&v;
            }

            // exchange with partner x-corner (lane ^ 4), x-lerp in half2
            unsigned int res[4];
            #pragma unroll
            for (int k = 0; k < 4; k++) {
                const unsigned int o = __shfl_xor_sync(0xffffffffu, ry[k], 4);
                const unsigned int ulo = isR ? o     : ry[k];   // x0 corner
                const unsigned int uhi = isR ? ry[k] : o;       // x1 corner
                const __half2 v = __hfma2(*(const __half2*)&uhi, wx2,
                                          __hmul2(*(const __half2*)&ulo, iwx2));
                res[k] = *(const unsigned int*)&v;
            }

            // partners hold identical res; each lane converts/stores only its
            // half: words {0,1} for left lanes, {2,3} for right lanes.
            if (live) {
                const unsigned int w0 = isR ? res[2] : res[0];
                const unsigned int w1 = isR ? res[3] : res[1];
                const float2 f0 = __half22float2(*(const __half2*)&w0);
                const float2 f1 = __half22float2(*(const __half2*)&w1);
                float4 v; v.x = f0.x; v.y = f0.y; v.z = f1.x; v.w = f1.y;
                // streaming store: write-once output must not evict scratch
                __stcs((float4*)(outp + (l * 3 + p) * 32), v);
            }
        }
    }
}

extern "C" void kernel_launch(void* const* d_in, const int* in_sizes, int n_in,
                              void* d_out, int out_size) {
    const float* pts = (const float*)d_in[0];
    const int n = in_sizes[0] / 3;  // 300000 points

    GridPtrs ptrs;
    for (int i = 0; i < 9; i++) ptrs.g[i] = (const float*)d_in[1 + i];

    transpose_all<<<TOTAL_TILES, 256>>>(ptrs);

    // 4 points per warp, 8 warps per block -> 32 points per block
    const int blocks = (n + 31) / 32;
    sample_kernel<<<blocks, 256>>>(pts, (float*)d_out, n);
}